// round 8
// baseline (speedup 1.0000x reference)
#include <cuda_runtime.h>
#include <math.h>

#define BROWS 16384
#define DDIM  256
#define TTRIP 262144
#define MARGIN 0.1f
#define EPSN   1e-6f

// Scratch (no allocations allowed in kernel_launch)
__device__ unsigned char g_predq[BROWS * DDIM];  // normalized int8 rows, 4 MB
__device__ float         g_scale[BROWS];         // per-row dequant step (maxabs/127)
__device__ double        g_accum;
__device__ unsigned      g_done = 0;             // last-block ticket (self-resetting)

// ---------------------------------------------------------------------------
// Kernel A: per-row inverse norm + normalize + per-row-scale int8 quant.
// One warp per TWO rows (4 front-batched LDG.128 per thread for MLP).
// Also zeroes the accumulator (graph replays re-run this).
// ---------------------------------------------------------------------------
__global__ void __launch_bounds__(256) normconv_kernel(const float* __restrict__ pred) {
    if (blockIdx.x == 0 && threadIdx.x == 0) g_accum = 0.0;

    int gw   = (blockIdx.x * blockDim.x + threadIdx.x) >> 5;  // warp id
    int lane = threadIdx.x & 31;
    int r0 = gw * 2;
    int r1 = r0 + 1;

    const float4* rowA = reinterpret_cast<const float4*>(pred + (size_t)r0 * DDIM);
    const float4* rowB = reinterpret_cast<const float4*>(pred + (size_t)r1 * DDIM);
    // front-batch all 4 loads (MLP=4)
    float4 a0 = rowA[lane * 2 + 0];
    float4 a1 = rowA[lane * 2 + 1];
    float4 b0 = rowB[lane * 2 + 0];
    float4 b1 = rowB[lane * 2 + 1];

    float ssA = a0.x*a0.x + a0.y*a0.y + a0.z*a0.z + a0.w*a0.w
              + a1.x*a1.x + a1.y*a1.y + a1.z*a1.z + a1.w*a1.w;
    float ssB = b0.x*b0.x + b0.y*b0.y + b0.z*b0.z + b0.w*b0.w
              + b1.x*b1.x + b1.y*b1.y + b1.z*b1.z + b1.w*b1.w;

    #pragma unroll
    for (int o = 16; o > 0; o >>= 1) {
        ssA += __shfl_xor_sync(0xFFFFFFFFu, ssA, o);
        ssB += __shfl_xor_sync(0xFFFFFFFFu, ssB, o);
    }

    float invA = 1.0f / fmaxf(sqrtf(ssA), EPSN);
    float invB = 1.0f / fmaxf(sqrtf(ssB), EPSN);

    float xa0 = a0.x*invA, xa1 = a0.y*invA, xa2 = a0.z*invA, xa3 = a0.w*invA;
    float xa4 = a1.x*invA, xa5 = a1.y*invA, xa6 = a1.z*invA, xa7 = a1.w*invA;
    float xb0 = b0.x*invB, xb1 = b0.y*invB, xb2 = b0.z*invB, xb3 = b0.w*invB;
    float xb4 = b1.x*invB, xb5 = b1.y*invB, xb6 = b1.z*invB, xb7 = b1.w*invB;

    float maA = fmaxf(fmaxf(fmaxf(fabsf(xa0), fabsf(xa1)), fmaxf(fabsf(xa2), fabsf(xa3))),
                      fmaxf(fmaxf(fabsf(xa4), fabsf(xa5)), fmaxf(fabsf(xa6), fabsf(xa7))));
    float maB = fmaxf(fmaxf(fmaxf(fabsf(xb0), fabsf(xb1)), fmaxf(fabsf(xb2), fabsf(xb3))),
                      fmaxf(fmaxf(fabsf(xb4), fabsf(xb5)), fmaxf(fabsf(xb6), fabsf(xb7))));
    float maxA = fmaxf(__uint_as_float(__reduce_max_sync(0xFFFFFFFFu, __float_as_uint(maA))), 1e-20f);
    float maxB = fmaxf(__uint_as_float(__reduce_max_sync(0xFFFFFFFFu, __float_as_uint(maB))), 1e-20f);

    float qsA = 127.0f / maxA;
    float qsB = 127.0f / maxB;

    uint2 pa, pb;
    {
        int q0 = __float2int_rn(xa0*qsA), q1 = __float2int_rn(xa1*qsA);
        int q2 = __float2int_rn(xa2*qsA), q3 = __float2int_rn(xa3*qsA);
        int q4 = __float2int_rn(xa4*qsA), q5 = __float2int_rn(xa5*qsA);
        int q6 = __float2int_rn(xa6*qsA), q7 = __float2int_rn(xa7*qsA);
        pa.x = (unsigned)(q0&0xFF) | ((unsigned)(q1&0xFF)<<8) | ((unsigned)(q2&0xFF)<<16) | ((unsigned)(q3&0xFF)<<24);
        pa.y = (unsigned)(q4&0xFF) | ((unsigned)(q5&0xFF)<<8) | ((unsigned)(q6&0xFF)<<16) | ((unsigned)(q7&0xFF)<<24);
    }
    {
        int q0 = __float2int_rn(xb0*qsB), q1 = __float2int_rn(xb1*qsB);
        int q2 = __float2int_rn(xb2*qsB), q3 = __float2int_rn(xb3*qsB);
        int q4 = __float2int_rn(xb4*qsB), q5 = __float2int_rn(xb5*qsB);
        int q6 = __float2int_rn(xb6*qsB), q7 = __float2int_rn(xb7*qsB);
        pb.x = (unsigned)(q0&0xFF) | ((unsigned)(q1&0xFF)<<8) | ((unsigned)(q2&0xFF)<<16) | ((unsigned)(q3&0xFF)<<24);
        pb.y = (unsigned)(q4&0xFF) | ((unsigned)(q5&0xFF)<<8) | ((unsigned)(q6&0xFF)<<16) | ((unsigned)(q7&0xFF)<<24);
    }

    reinterpret_cast<uint2*>(g_predq + (size_t)r0 * DDIM)[lane] = pa;
    reinterpret_cast<uint2*>(g_predq + (size_t)r1 * DDIM)[lane] = pb;

    if (lane == 0) g_scale[r0] = maxA * (1.0f / 127.0f);
    if (lane == 1) g_scale[r1] = maxB * (1.0f / 127.0f);
}

// ---------------------------------------------------------------------------
// Kernel B: 2048 blocks x 8 warps; each warp processes 16 consecutive triplets.
// dp4a dual dot + REDUX warp-sum + dequant + relu. One double atomicAdd per
// block, and the LAST block to finish writes the mean (fused finalize).
// ---------------------------------------------------------------------------
#define TRIP_PER_WARP 16

__global__ void __launch_bounds__(256) triplet_kernel(
    const int* __restrict__ aidx,
    const int* __restrict__ pidx,
    const int* __restrict__ nidx,
    float* __restrict__ out)
{
    int gw   = (blockIdx.x * blockDim.x + threadIdx.x) >> 5;  // global warp
    int lane = threadIdx.x & 31;
    int wib  = threadIdx.x >> 5;

    __shared__ float part[8];

    int base = gw * TRIP_PER_WARP;
    float acc = 0.0f;

    #pragma unroll 2
    for (int i = 0; i < TRIP_PER_WARP; i++) {
        int t = base + i;
        int a = aidx[t];
        int p = pidx[t];
        int n = nidx[t];

        const uint2* ra = reinterpret_cast<const uint2*>(g_predq + (size_t)a * DDIM);
        const uint2* rp = reinterpret_cast<const uint2*>(g_predq + (size_t)p * DDIM);
        const uint2* rn = reinterpret_cast<const uint2*>(g_predq + (size_t)n * DDIM);

        uint2 av = ra[lane];
        uint2 pv = rp[lane];
        uint2 nv = rn[lane];

        int dap = __dp4a((int)av.x, (int)pv.x, 0);
        dap     = __dp4a((int)av.y, (int)pv.y, dap);
        int dan = __dp4a((int)av.x, (int)nv.x, 0);
        dan     = __dp4a((int)av.y, (int)nv.y, dan);

        dap = __reduce_add_sync(0xFFFFFFFFu, dap);
        dan = __reduce_add_sync(0xFFFFFFFFu, dan);

        float sa = g_scale[a];
        float sp = g_scale[p];
        float sn = g_scale[n];
        float v = (float)dap * (sa * sp) - (float)dan * (sa * sn) + MARGIN;
        acc += fmaxf(v, 0.0f);
    }

    if (lane == 0) part[wib] = acc;
    __syncthreads();

    if (threadIdx.x == 0) {
        float s = 0.0f;
        #pragma unroll
        for (int i = 0; i < 8; i++) s += part[i];
        atomicAdd(&g_accum, (double)s);
        __threadfence();
        unsigned ticket = atomicAdd(&g_done, 1u);
        if (ticket == gridDim.x - 1) {
            g_done = 0;  // reset for next graph replay
            out[0] = (float)(g_accum / (double)TTRIP);
        }
    }
}

extern "C" void kernel_launch(void* const* d_in, const int* in_sizes, int n_in,
                              void* d_out, int out_size) {
    const float* pred = (const float*)d_in[0];
    const int*   ai   = (const int*)d_in[1];
    const int*   pi   = (const int*)d_in[2];
    const int*   ni   = (const int*)d_in[3];
    float* out = (float*)d_out;

    normconv_kernel<<<BROWS / 16, 256>>>(pred);                        // 1024 blocks, 2 rows/warp
    triplet_kernel<<<TTRIP / (8 * TRIP_PER_WARP), 256>>>(ai, pi, ni, out); // 2048 blocks
}

// round 9
// speedup vs baseline: 1.0689x; 1.0689x over previous
#include <cuda_runtime.h>
#include <math.h>

#define BROWS 16384
#define DDIM  256
#define TTRIP 262144
#define MARGIN 0.1f
#define EPSN   1e-6f

// Scratch (no allocations allowed in kernel_launch)
__device__ unsigned char g_predq[BROWS * DDIM];  // normalized int8 rows, 4 MB
__device__ float         g_scale[BROWS];         // per-row dequant step (maxabs/127)
__device__ double        g_accum;

// ---------------------------------------------------------------------------
// Kernel A: per-row inverse norm + normalize + per-row-scale int8 quant.
// One warp per TWO rows (4 front-batched LDG.128 per thread for MLP).
// Also zeroes the accumulator (graph replays re-run this).
// ---------------------------------------------------------------------------
__global__ void __launch_bounds__(256) normconv_kernel(const float* __restrict__ pred) {
    if (blockIdx.x == 0 && threadIdx.x == 0) g_accum = 0.0;

    int gw   = (blockIdx.x * blockDim.x + threadIdx.x) >> 5;  // warp id
    int lane = threadIdx.x & 31;
    int r0 = gw * 2;
    int r1 = r0 + 1;

    const float4* rowA = reinterpret_cast<const float4*>(pred + (size_t)r0 * DDIM);
    const float4* rowB = reinterpret_cast<const float4*>(pred + (size_t)r1 * DDIM);
    float4 a0 = rowA[lane * 2 + 0];
    float4 a1 = rowA[lane * 2 + 1];
    float4 b0 = rowB[lane * 2 + 0];
    float4 b1 = rowB[lane * 2 + 1];

    float ssA = a0.x*a0.x + a0.y*a0.y + a0.z*a0.z + a0.w*a0.w
              + a1.x*a1.x + a1.y*a1.y + a1.z*a1.z + a1.w*a1.w;
    float ssB = b0.x*b0.x + b0.y*b0.y + b0.z*b0.z + b0.w*b0.w
              + b1.x*b1.x + b1.y*b1.y + b1.z*b1.z + b1.w*b1.w;

    #pragma unroll
    for (int o = 16; o > 0; o >>= 1) {
        ssA += __shfl_xor_sync(0xFFFFFFFFu, ssA, o);
        ssB += __shfl_xor_sync(0xFFFFFFFFu, ssB, o);
    }

    float invA = 1.0f / fmaxf(sqrtf(ssA), EPSN);
    float invB = 1.0f / fmaxf(sqrtf(ssB), EPSN);

    float xa0 = a0.x*invA, xa1 = a0.y*invA, xa2 = a0.z*invA, xa3 = a0.w*invA;
    float xa4 = a1.x*invA, xa5 = a1.y*invA, xa6 = a1.z*invA, xa7 = a1.w*invA;
    float xb0 = b0.x*invB, xb1 = b0.y*invB, xb2 = b0.z*invB, xb3 = b0.w*invB;
    float xb4 = b1.x*invB, xb5 = b1.y*invB, xb6 = b1.z*invB, xb7 = b1.w*invB;

    float maA = fmaxf(fmaxf(fmaxf(fabsf(xa0), fabsf(xa1)), fmaxf(fabsf(xa2), fabsf(xa3))),
                      fmaxf(fmaxf(fabsf(xa4), fabsf(xa5)), fmaxf(fabsf(xa6), fabsf(xa7))));
    float maB = fmaxf(fmaxf(fmaxf(fabsf(xb0), fabsf(xb1)), fmaxf(fabsf(xb2), fabsf(xb3))),
                      fmaxf(fmaxf(fabsf(xb4), fabsf(xb5)), fmaxf(fabsf(xb6), fabsf(xb7))));
    float maxA = fmaxf(__uint_as_float(__reduce_max_sync(0xFFFFFFFFu, __float_as_uint(maA))), 1e-20f);
    float maxB = fmaxf(__uint_as_float(__reduce_max_sync(0xFFFFFFFFu, __float_as_uint(maB))), 1e-20f);

    float qsA = 127.0f / maxA;
    float qsB = 127.0f / maxB;

    uint2 pa, pb;
    {
        int q0 = __float2int_rn(xa0*qsA), q1 = __float2int_rn(xa1*qsA);
        int q2 = __float2int_rn(xa2*qsA), q3 = __float2int_rn(xa3*qsA);
        int q4 = __float2int_rn(xa4*qsA), q5 = __float2int_rn(xa5*qsA);
        int q6 = __float2int_rn(xa6*qsA), q7 = __float2int_rn(xa7*qsA);
        pa.x = (unsigned)(q0&0xFF) | ((unsigned)(q1&0xFF)<<8) | ((unsigned)(q2&0xFF)<<16) | ((unsigned)(q3&0xFF)<<24);
        pa.y = (unsigned)(q4&0xFF) | ((unsigned)(q5&0xFF)<<8) | ((unsigned)(q6&0xFF)<<16) | ((unsigned)(q7&0xFF)<<24);
    }
    {
        int q0 = __float2int_rn(xb0*qsB), q1 = __float2int_rn(xb1*qsB);
        int q2 = __float2int_rn(xb2*qsB), q3 = __float2int_rn(xb3*qsB);
        int q4 = __float2int_rn(xb4*qsB), q5 = __float2int_rn(xb5*qsB);
        int q6 = __float2int_rn(xb6*qsB), q7 = __float2int_rn(xb7*qsB);
        pb.x = (unsigned)(q0&0xFF) | ((unsigned)(q1&0xFF)<<8) | ((unsigned)(q2&0xFF)<<16) | ((unsigned)(q3&0xFF)<<24);
        pb.y = (unsigned)(q4&0xFF) | ((unsigned)(q5&0xFF)<<8) | ((unsigned)(q6&0xFF)<<16) | ((unsigned)(q7&0xFF)<<24);
    }

    reinterpret_cast<uint2*>(g_predq + (size_t)r0 * DDIM)[lane] = pa;
    reinterpret_cast<uint2*>(g_predq + (size_t)r1 * DDIM)[lane] = pb;

    if (lane == 0) g_scale[r0] = maxA * (1.0f / 127.0f);
    if (lane == 1) g_scale[r1] = maxB * (1.0f / 127.0f);
}

// ---------------------------------------------------------------------------
// Kernel B: half-warp-per-triplet. Each warp iteration handles TWO triplets:
// lanes 0-15 -> triplet 2i, lanes 16-31 -> triplet 2i+1. Each lane loads one
// uint4 (16B) so one LDG.128 fetches a 256B row for each half simultaneously.
// Segmented __reduce_add_sync per half. One double atomicAdd per block.
// ---------------------------------------------------------------------------
#define ITERS 16   // triplets per warp = 2*ITERS = 32

__global__ void __launch_bounds__(256) triplet_kernel(
    const int* __restrict__ aidx,
    const int* __restrict__ pidx,
    const int* __restrict__ nidx)
{
    int gw     = (blockIdx.x * blockDim.x + threadIdx.x) >> 5;  // global warp
    int lane   = threadIdx.x & 31;
    int half   = lane >> 4;          // 0 or 1
    int lane16 = lane & 15;
    int wib    = threadIdx.x >> 5;

    unsigned hmask = half ? 0xFFFF0000u : 0x0000FFFFu;

    __shared__ float part[16];

    int base = gw * (2 * ITERS);
    float acc = 0.0f;

    #pragma unroll 2
    for (int i = 0; i < ITERS; i++) {
        int t = base + 2 * i + half;
        int a = aidx[t];
        int p = pidx[t];
        int n = nidx[t];

        const uint4* ra = reinterpret_cast<const uint4*>(g_predq + (size_t)a * DDIM);
        const uint4* rp = reinterpret_cast<const uint4*>(g_predq + (size_t)p * DDIM);
        const uint4* rn = reinterpret_cast<const uint4*>(g_predq + (size_t)n * DDIM);

        uint4 av = ra[lane16];
        uint4 pv = rp[lane16];
        uint4 nv = rn[lane16];

        int dap = __dp4a((int)av.x, (int)pv.x, 0);
        dap     = __dp4a((int)av.y, (int)pv.y, dap);
        dap     = __dp4a((int)av.z, (int)pv.z, dap);
        dap     = __dp4a((int)av.w, (int)pv.w, dap);
        int dan = __dp4a((int)av.x, (int)nv.x, 0);
        dan     = __dp4a((int)av.y, (int)nv.y, dan);
        dan     = __dp4a((int)av.z, (int)nv.z, dan);
        dan     = __dp4a((int)av.w, (int)nv.w, dan);

        dap = __reduce_add_sync(hmask, dap);
        dan = __reduce_add_sync(hmask, dan);

        float sa = g_scale[a];
        float sp = g_scale[p];
        float sn = g_scale[n];
        float v = (float)dap * (sa * sp) - (float)dan * (sa * sn) + MARGIN;
        acc += fmaxf(v, 0.0f);
    }

    // acc is uniform within each half-warp
    if (lane16 == 0) part[wib * 2 + half] = acc;
    __syncthreads();

    if (threadIdx.x == 0) {
        float s = 0.0f;
        #pragma unroll
        for (int i = 0; i < 16; i++) s += part[i];
        atomicAdd(&g_accum, (double)s);
    }
}

// ---------------------------------------------------------------------------
// Kernel C: finalize the mean
// ---------------------------------------------------------------------------
__global__ void finalize_kernel(float* __restrict__ out) {
    out[0] = (float)(g_accum / (double)TTRIP);
}

extern "C" void kernel_launch(void* const* d_in, const int* in_sizes, int n_in,
                              void* d_out, int out_size) {
    const float* pred = (const float*)d_in[0];
    const int*   ai   = (const int*)d_in[1];
    const int*   pi   = (const int*)d_in[2];
    const int*   ni   = (const int*)d_in[3];
    float* out = (float*)d_out;

    normconv_kernel<<<BROWS / 16, 256>>>(pred);                      // 1024 blocks, 2 rows/warp
    triplet_kernel<<<TTRIP / (8 * 2 * ITERS), 256>>>(ai, pi, ni);    // 1024 blocks, 32 trip/warp
    finalize_kernel<<<1, 1>>>(out);
}